// round 4
// baseline (speedup 1.0000x reference)
#include <cuda_runtime.h>
#include <math.h>
#include <stdint.h>

// INGP hashgrid encoding with spatial bucket-sort for coarse-level coalescing.
//
// Pipeline (one CUDA graph, 6 kernels):
//   1. zero      : clear 32K-bucket histogram
//   2. hist      : Morton-cell key per point (res-32 grid) + histogram
//   3. scan      : exclusive prefix sum over 32768 buckets (single block)
//   4. scatter   : counting-sort permutation g_perm (sorted -> original idx)
//   5. coarse    : levels 0-7, lane = sorted point -> warp lanes are spatial
//                  neighbors, corner gathers merge in the coalescer (1 wavefront
//                  per distinct 32B sector instead of per lane) and hit L1.
//   6. fine      : levels 8-15, 8 threads/point (no coherence possible at
//                  res>=153) -> coalesced stores, even-ix float4 pairing, .cg.

#define NPTS   524288
#define NLEV   16
#define TSIZE  (1u << 19)
#define HMASK  (TSIZE - 1u)
#define PRIME1 2654435761u
#define PRIME2 805459861u
#define NB     32768            // 32^3 Morton buckets

struct ResArr { float r[NLEV]; };

__device__ unsigned g_hist[NB];
__device__ unsigned g_off[NB];
__device__ unsigned g_keys[NPTS];
__device__ unsigned g_perm[NPTS];

// ---------------- sort helpers ----------------

__device__ __forceinline__ uint32_t p1b2(uint32_t x) {   // spread 10 bits
    x &= 0x3FFu;
    x = (x | (x << 16)) & 0x030000FFu;
    x = (x | (x <<  8)) & 0x0300F00Fu;
    x = (x | (x <<  4)) & 0x030C30C3u;
    x = (x | (x <<  2)) & 0x09249249u;
    return x;
}

__global__ void zero_kernel()
{
    int i = blockIdx.x * blockDim.x + threadIdx.x;
    if (i < NB) g_hist[i] = 0;
}

__global__ void hist_kernel(const float* __restrict__ pts)
{
    int t = blockIdx.x * blockDim.x + threadIdx.x;
    if (t >= NPTS) return;
    float xs = (pts[3 * t + 0] + 1.0f) * 0.5f;
    float ys = (pts[3 * t + 1] + 1.0f) * 0.5f;
    float zs = (pts[3 * t + 2] + 1.0f) * 0.5f;
    int cx = min(31, max(0, (int)(xs * 32.0f)));
    int cy = min(31, max(0, (int)(ys * 32.0f)));
    int cz = min(31, max(0, (int)(zs * 32.0f)));
    uint32_t key = p1b2((uint32_t)cx) | (p1b2((uint32_t)cy) << 1) | (p1b2((uint32_t)cz) << 2);
    g_keys[t] = key;
    atomicAdd(&g_hist[key], 1u);
}

__global__ void scan_kernel()            // <<<1, 1024>>>, 32 buckets/thread
{
    __shared__ unsigned s[1024];
    int tid = threadIdx.x;
    unsigned loc[32];
    unsigned sum = 0;
    #pragma unroll
    for (int j = 0; j < 32; j++) { loc[j] = g_hist[tid * 32 + j]; sum += loc[j]; }
    s[tid] = sum;
    __syncthreads();
    // Hillis-Steele inclusive scan over 1024 chunk sums
    for (int off = 1; off < 1024; off <<= 1) {
        unsigned v = (tid >= off) ? s[tid - off] : 0u;
        __syncthreads();
        s[tid] += v;
        __syncthreads();
    }
    unsigned run = s[tid] - sum;         // exclusive prefix of this chunk
    #pragma unroll
    for (int j = 0; j < 32; j++) { g_off[tid * 32 + j] = run; run += loc[j]; }
}

__global__ void scatter_kernel()
{
    int t = blockIdx.x * blockDim.x + threadIdx.x;
    if (t >= NPTS) return;
    unsigned key = g_keys[t];
    unsigned pos = atomicAdd(&g_off[key], 1u);
    g_perm[pos] = (unsigned)t;
}

// ---------------- per-level gather/interpolate ----------------

template <bool CG>
__device__ __forceinline__ float2 level_feat(
    float xs, float ys, float zs, float r, const float2* __restrict__ tab)
{
    float posx = __fmul_rn(xs, r);
    float posy = __fmul_rn(ys, r);
    float posz = __fmul_rn(zs, r);

    float fx = floorf(posx), fy = floorf(posy), fz = floorf(posz);
    float wx = __fsub_rn(posx, fx);
    float wy = __fsub_rn(posy, fy);
    float wz = __fsub_rn(posz, fz);

    uint32_t ix = (uint32_t)fx;
    uint32_t iy = (uint32_t)fy;
    uint32_t iz = (uint32_t)fz;

    uint32_t hy0 = iy * PRIME1;
    uint32_t hy1 = hy0 + PRIME1;
    uint32_t hz0 = iz * PRIME2;
    uint32_t hz1 = hz0 + PRIME2;
    uint32_t rest[4];
    rest[0] = hy0 ^ hz0;
    rest[1] = hy0 ^ hz1;
    rest[2] = hy1 ^ hz0;
    rest[3] = hy1 ^ hz1;

    float2 v0[4], v1[4];
    if ((ix & 1u) == 0u) {
        // even ix: x-corners h and h^1 share one aligned float4
        const float4* tab4 = (const float4*)tab;
        #pragma unroll
        for (int i = 0; i < 4; i++) {
            uint32_t b = (ix ^ rest[i]) & HMASK;
            float4 q = CG ? __ldcg(tab4 + (b >> 1)) : __ldg(tab4 + (b >> 1));
            bool lo = (b & 1u) == 0u;
            v0[i] = lo ? make_float2(q.x, q.y) : make_float2(q.z, q.w);
            v1[i] = lo ? make_float2(q.z, q.w) : make_float2(q.x, q.y);
        }
    } else {
        uint32_t ix1 = ix + 1u;
        #pragma unroll
        for (int i = 0; i < 4; i++) {
            v0[i] = CG ? __ldcg(tab + ((ix  ^ rest[i]) & HMASK))
                       : __ldg (tab + ((ix  ^ rest[i]) & HMASK));
            v1[i] = CG ? __ldcg(tab + ((ix1 ^ rest[i]) & HMASK))
                       : __ldg (tab + ((ix1 ^ rest[i]) & HMASK));
        }
    }

    float ux0 = 1.0f - wx, ux1 = wx;
    float uy0 = 1.0f - wy, uy1 = wy;
    float uz0 = 1.0f - wz, uz1 = wz;

    float w000 = ux0 * uy0 * uz0;
    float w001 = ux0 * uy0 * uz1;
    float w010 = ux0 * uy1 * uz0;
    float w011 = ux0 * uy1 * uz1;
    float w100 = ux1 * uy0 * uz0;
    float w101 = ux1 * uy0 * uz1;
    float w110 = ux1 * uy1 * uz0;
    float w111 = ux1 * uy1 * uz1;

    float2 acc;
    acc.x = w000 * v0[0].x + w001 * v0[1].x + w010 * v0[2].x + w011 * v0[3].x
          + w100 * v1[0].x + w101 * v1[1].x + w110 * v1[2].x + w111 * v1[3].x;
    acc.y = w000 * v0[0].y + w001 * v0[1].y + w010 * v0[2].y + w011 * v0[3].y
          + w100 * v1[0].y + w101 * v1[1].y + w110 * v1[2].y + w111 * v1[3].y;
    return acc;
}

// ---------------- coarse kernel: levels 0-7, lane = sorted point ----------------

__global__ __launch_bounds__(256) void ingp_coarse_kernel(
    const float*  __restrict__ pts,
    const float2* __restrict__ tables,
    float2*       __restrict__ out,
    ResArr res)
{
    int t = blockIdx.x * blockDim.x + threadIdx.x;     // 0..NPTS-1, sorted order
    unsigned p = g_perm[t];                            // original point index

    float px = pts[3 * p + 0];
    float py = pts[3 * p + 1];
    float pz = pts[3 * p + 2];
    float xs = __fmul_rn(__fadd_rn(px, 1.0f), 0.5f);
    float ys = __fmul_rn(__fadd_rn(py, 1.0f), 0.5f);
    float zs = __fmul_rn(__fadd_rn(pz, 1.0f), 0.5f);

    float2 feats[8];
    #pragma unroll
    for (int l = 0; l < 8; l++)
        feats[l] = level_feat<false>(xs, ys, zs, res.r[l], tables + (size_t)l * TSIZE);

    // levels 0-7 = first 64B of the point's 128B output row
    float4* ob = (float4*)(out + (size_t)p * NLEV);
    #pragma unroll
    for (int i = 0; i < 4; i++)
        ob[i] = make_float4(feats[2*i].x, feats[2*i].y, feats[2*i+1].x, feats[2*i+1].y);
}

// ---------------- fine kernel: levels 8-15, 8 threads/point ----------------

__global__ __launch_bounds__(256) void ingp_fine_kernel(
    const float*  __restrict__ pts,
    const float2* __restrict__ tables,
    float2*       __restrict__ out,
    ResArr res)
{
    int t = blockIdx.x * blockDim.x + threadIdx.x;
    int n = t >> 3;              // point
    int l = 8 + (t & 7);         // level 8..15

    float px = pts[3 * n + 0];   // 8 lanes share -> broadcast
    float py = pts[3 * n + 1];
    float pz = pts[3 * n + 2];
    float xs = __fmul_rn(__fadd_rn(px, 1.0f), 0.5f);
    float ys = __fmul_rn(__fadd_rn(py, 1.0f), 0.5f);
    float zs = __fmul_rn(__fadd_rn(pz, 1.0f), 0.5f);

    float2 acc = level_feat<true>(xs, ys, zs, res.r[l], tables + (size_t)l * TSIZE);

    out[(size_t)n * NLEV + l] = acc;   // 8 consecutive float2 per point group
}

// ---------------- host ----------------

extern "C" void kernel_launch(void* const* d_in, const int* in_sizes, int n_in,
                              void* d_out, int out_size)
{
    const float*  pts    = (const float*)d_in[0];   // [N,3]
    const float2* tables = (const float2*)d_in[1];  // [L,T,2] -> [L,T] float2
    float2*       out    = (float2*)d_out;

    // Replicate numpy RES exactly (float64 libm chain)
    ResArr res;
    {
        double growth = exp((log(2048.0) - log(16.0)) / 15.0);
        for (int l = 0; l < NLEV; l++)
            res.r[l] = (float)floor(16.0 * pow(growth, (double)l));
    }

    zero_kernel   <<<(NB + 1023) / 1024, 1024>>>();
    hist_kernel   <<<NPTS / 256, 256>>>(pts);
    scan_kernel   <<<1, 1024>>>();
    scatter_kernel<<<NPTS / 256, 256>>>();
    ingp_coarse_kernel<<<NPTS / 256, 256>>>(pts, tables, out, res);
    ingp_fine_kernel  <<<NPTS * 8 / 256, 256>>>(pts, tables, out, res);
}

// round 8
// speedup vs baseline: 1.0735x; 1.0735x over previous
#include <cuda_runtime.h>
#include <math.h>
#include <stdint.h>

// INGP hashgrid encoding.
//   out[n, l*2+f] = sum_{8 corners} w_c * tables[l, hash(corner)&(T-1), f]
// N=524288, L=16, T=2^19, F=2.
//
// Split:
//  - levels 0-3 (res 16..42): bucket-binned coarse kernel. Points are binned
//    into a 32^3 grid with 32 slots/bucket; one WARP = one bucket, so all
//    lanes of a corner-gather instruction are spatial neighbors and merge in
//    the l1tex coalescer (distinct cells per warp << 32 at these res).
//  - levels 4-15: 12 threads/point, coalesced 96B stores, even-ix float4
//    pairing (hash uses prime 1 on x: even ix -> x-corners at h and h^1 share
//    one aligned float4), .cg to keep L1 for the coarse tables.

#define NPTS   524288
#define NLEV   16
#define TSIZE  (1u << 19)
#define HMASK  (TSIZE - 1u)
#define PRIME1 2654435761u
#define PRIME2 805459861u

#define NB     32768          // 32^3 buckets
#define CAP    32             // slots per bucket (= warp size)
#define NSLOTS (NB * CAP)     // 1048576

struct ResArr { float r[NLEV]; };

__device__ unsigned g_cnt[NB];
__device__ unsigned g_ovcnt;
__device__ unsigned g_ov[NPTS];
__device__ float4   g_spts[NSLOTS];   // xs,ys,zs normalized; w = point idx bits

// ---------------- binning ----------------

__global__ void zero_kernel()
{
    int i = blockIdx.x * blockDim.x + threadIdx.x;
    if (i < NB) g_cnt[i] = 0;
    if (i == NB) g_ovcnt = 0;
}

__global__ void bin_kernel(const float* __restrict__ pts)
{
    int t = blockIdx.x * blockDim.x + threadIdx.x;
    if (t >= NPTS) return;
    float px = pts[3 * t + 0];
    float py = pts[3 * t + 1];
    float pz = pts[3 * t + 2];
    // exact normalization (same ops as compute kernels -> bit-identical)
    float xs = __fmul_rn(__fadd_rn(px, 1.0f), 0.5f);
    float ys = __fmul_rn(__fadd_rn(py, 1.0f), 0.5f);
    float zs = __fmul_rn(__fadd_rn(pz, 1.0f), 0.5f);

    int cx = min(31, max(0, (int)(xs * 32.0f)));
    int cy = min(31, max(0, (int)(ys * 32.0f)));
    int cz = min(31, max(0, (int)(zs * 32.0f)));
    int b = (cx << 10) | (cy << 5) | cz;

    unsigned c = atomicAdd(&g_cnt[b], 1u);
    if (c < CAP) {
        float4 v;
        v.x = xs; v.y = ys; v.z = zs; v.w = __uint_as_float((unsigned)t);
        g_spts[b * CAP + c] = v;
    } else {
        unsigned o = atomicAdd(&g_ovcnt, 1u);
        g_ov[o] = (unsigned)t;
    }
}

// ---------------- per-level gather/interpolate (exact ops) ----------------

template <bool CG>
__device__ __forceinline__ float2 level_feat(
    float xs, float ys, float zs, float r, const float2* __restrict__ tab)
{
    float posx = __fmul_rn(xs, r);
    float posy = __fmul_rn(ys, r);
    float posz = __fmul_rn(zs, r);

    float fx = floorf(posx), fy = floorf(posy), fz = floorf(posz);
    float wx = __fsub_rn(posx, fx);
    float wy = __fsub_rn(posy, fy);
    float wz = __fsub_rn(posz, fz);

    uint32_t ix = (uint32_t)fx;
    uint32_t iy = (uint32_t)fy;
    uint32_t iz = (uint32_t)fz;

    uint32_t hy0 = iy * PRIME1;
    uint32_t hy1 = hy0 + PRIME1;
    uint32_t hz0 = iz * PRIME2;
    uint32_t hz1 = hz0 + PRIME2;
    uint32_t rest[4];
    rest[0] = hy0 ^ hz0;
    rest[1] = hy0 ^ hz1;
    rest[2] = hy1 ^ hz0;
    rest[3] = hy1 ^ hz1;

    float2 v0[4], v1[4];
    if ((ix & 1u) == 0u) {
        const float4* tab4 = (const float4*)tab;
        #pragma unroll
        for (int i = 0; i < 4; i++) {
            uint32_t b = (ix ^ rest[i]) & HMASK;
            float4 q = CG ? __ldcg(tab4 + (b >> 1)) : __ldg(tab4 + (b >> 1));
            bool lo = (b & 1u) == 0u;
            v0[i] = lo ? make_float2(q.x, q.y) : make_float2(q.z, q.w);
            v1[i] = lo ? make_float2(q.z, q.w) : make_float2(q.x, q.y);
        }
    } else {
        uint32_t ix1 = ix + 1u;
        #pragma unroll
        for (int i = 0; i < 4; i++) {
            v0[i] = CG ? __ldcg(tab + ((ix  ^ rest[i]) & HMASK))
                       : __ldg (tab + ((ix  ^ rest[i]) & HMASK));
            v1[i] = CG ? __ldcg(tab + ((ix1 ^ rest[i]) & HMASK))
                       : __ldg (tab + ((ix1 ^ rest[i]) & HMASK));
        }
    }

    float ux0 = 1.0f - wx, ux1 = wx;
    float uy0 = 1.0f - wy, uy1 = wy;
    float uz0 = 1.0f - wz, uz1 = wz;

    float w000 = ux0 * uy0 * uz0;
    float w001 = ux0 * uy0 * uz1;
    float w010 = ux0 * uy1 * uz0;
    float w011 = ux0 * uy1 * uz1;
    float w100 = ux1 * uy0 * uz0;
    float w101 = ux1 * uy0 * uz1;
    float w110 = ux1 * uy1 * uz0;
    float w111 = ux1 * uy1 * uz1;

    float2 acc;
    acc.x = w000 * v0[0].x + w001 * v0[1].x + w010 * v0[2].x + w011 * v0[3].x
          + w100 * v1[0].x + w101 * v1[1].x + w110 * v1[2].x + w111 * v1[3].x;
    acc.y = w000 * v0[0].y + w001 * v0[1].y + w010 * v0[2].y + w011 * v0[3].y
          + w100 * v1[0].y + w101 * v1[1].y + w110 * v1[2].y + w111 * v1[3].y;
    return acc;
}

// ---------------- coarse: levels 0-3, one warp = one bucket ----------------

__global__ __launch_bounds__(256) void ingp_coarse_kernel(
    const float2* __restrict__ tables,
    float2*       __restrict__ out,
    ResArr res)
{
    int t = blockIdx.x * blockDim.x + threadIdx.x;   // NSLOTS threads
    int b = t >> 5;                                  // bucket = warp id
    int j = t & 31;
    unsigned c = g_cnt[b];
    if (j >= (int)min(c, (unsigned)CAP)) return;

    float4 P = g_spts[t];
    unsigned p = __float_as_uint(P.w);

    float2 f0 = level_feat<false>(P.x, P.y, P.z, res.r[0], tables);
    float2 f1 = level_feat<false>(P.x, P.y, P.z, res.r[1], tables + (size_t)1 * TSIZE);
    float2 f2 = level_feat<false>(P.x, P.y, P.z, res.r[2], tables + (size_t)2 * TSIZE);
    float2 f3 = level_feat<false>(P.x, P.y, P.z, res.r[3], tables + (size_t)3 * TSIZE);

    float4* ob = (float4*)(out + (size_t)p * NLEV);  // 32B = levels 0-3
    ob[0] = make_float4(f0.x, f0.y, f1.x, f1.y);
    ob[1] = make_float4(f2.x, f2.y, f3.x, f3.y);
}

// ---------------- overflow: levels 0-3 for spilled points ----------------

__global__ void ingp_overflow_kernel(
    const float*  __restrict__ pts,
    const float2* __restrict__ tables,
    float2*       __restrict__ out,
    ResArr res)
{
    unsigned n_ov = g_ovcnt;
    int stride = gridDim.x * blockDim.x;
    for (unsigned i = blockIdx.x * blockDim.x + threadIdx.x; i < n_ov; i += stride) {
        unsigned p = g_ov[i];
        float xs = __fmul_rn(__fadd_rn(pts[3 * p + 0], 1.0f), 0.5f);
        float ys = __fmul_rn(__fadd_rn(pts[3 * p + 1], 1.0f), 0.5f);
        float zs = __fmul_rn(__fadd_rn(pts[3 * p + 2], 1.0f), 0.5f);
        float2 f0 = level_feat<false>(xs, ys, zs, res.r[0], tables);
        float2 f1 = level_feat<false>(xs, ys, zs, res.r[1], tables + (size_t)1 * TSIZE);
        float2 f2 = level_feat<false>(xs, ys, zs, res.r[2], tables + (size_t)2 * TSIZE);
        float2 f3 = level_feat<false>(xs, ys, zs, res.r[3], tables + (size_t)3 * TSIZE);
        float4* ob = (float4*)(out + (size_t)p * NLEV);
        ob[0] = make_float4(f0.x, f0.y, f1.x, f1.y);
        ob[1] = make_float4(f2.x, f2.y, f3.x, f3.y);
    }
}

// ---------------- fine: levels 4-15, 12 threads per point ----------------

__global__ __launch_bounds__(256) void ingp_fine_kernel(
    const float*  __restrict__ pts,
    const float2* __restrict__ tables,
    float2*       __restrict__ out,
    ResArr res)
{
    int t = blockIdx.x * blockDim.x + threadIdx.x;   // NPTS*12, exact grid
    int n = t / 12;
    int l = 4 + (t - n * 12);

    float px = pts[3 * n + 0];   // 12 lanes share -> broadcast
    float py = pts[3 * n + 1];
    float pz = pts[3 * n + 2];
    float xs = __fmul_rn(__fadd_rn(px, 1.0f), 0.5f);
    float ys = __fmul_rn(__fadd_rn(py, 1.0f), 0.5f);
    float zs = __fmul_rn(__fadd_rn(pz, 1.0f), 0.5f);

    float2 acc = level_feat<true>(xs, ys, zs, res.r[l], tables + (size_t)l * TSIZE);

    out[(size_t)n * NLEV + l] = acc;   // 12 consecutive float2 per point
}

// ---------------- host ----------------

extern "C" void kernel_launch(void* const* d_in, const int* in_sizes, int n_in,
                              void* d_out, int out_size)
{
    const float*  pts    = (const float*)d_in[0];   // [N,3]
    const float2* tables = (const float2*)d_in[1];  // [L,T,2] -> [L,T] float2
    float2*       out    = (float2*)d_out;

    // Replicate numpy RES exactly (float64 libm chain)
    ResArr res;
    {
        double growth = exp((log(2048.0) - log(16.0)) / 15.0);
        for (int l = 0; l < NLEV; l++)
            res.r[l] = (float)floor(16.0 * pow(growth, (double)l));
    }

    zero_kernel<<<(NB + 1 + 1023) / 1024, 1024>>>();
    bin_kernel <<<NPTS / 256, 256>>>(pts);
    ingp_coarse_kernel  <<<NSLOTS / 256, 256>>>(tables, out, res);
    ingp_overflow_kernel<<<32, 256>>>(pts, tables, out, res);
    ingp_fine_kernel    <<<NPTS * 12 / 256, 256>>>(pts, tables, out, res);
}

// round 9
// speedup vs baseline: 1.1071x; 1.0313x over previous
#include <cuda_runtime.h>
#include <math.h>
#include <stdint.h>

// INGP hashgrid encoding.
//   out[n, l*2+f] = sum_{8 corners} w_c * tables[l, hash(corner)&(T-1), f]
// N=524288, L=16, T=2^19, F=2.
//
// Levels 0-3: bucket-binned coarse kernel. Points binned into a 32^3 grid,
// 32 slots/bucket, one WARP = one bucket -> all lanes of a corner-gather are
// spatial neighbors; at res<=42 they collapse to 1-8 sectors per instruction
// in the l1tex coalescer (vs 32 when unsorted). Overflow points are processed
// by the same kernel (fused tail), no extra launch.
// Levels 4-15: 12 threads/point, coalesced stores, even-ix float4 pairing, .cg.

#define NPTS   524288
#define NLEV   16
#define TSIZE  (1u << 19)
#define HMASK  (TSIZE - 1u)
#define PRIME1 2654435761u
#define PRIME2 805459861u

#define NB     32768          // 32^3 buckets
#define CAP    32             // slots per bucket (= warp size)
#define NSLOTS (NB * CAP)     // 1048576

struct ResArr { float r[NLEV]; };

__device__ unsigned g_cnt[NB];
__device__ unsigned g_ovcnt;
__device__ unsigned g_ov[NPTS];
__device__ float4   g_spts[NSLOTS];   // xs,ys,zs normalized; w = point idx bits

// ---------------- binning ----------------

__global__ void zero_kernel()
{
    int i = blockIdx.x * blockDim.x + threadIdx.x;
    if (i < NB) g_cnt[i] = 0;
    if (i == NB) g_ovcnt = 0;
}

__global__ void bin_kernel(const float* __restrict__ pts)
{
    int t = blockIdx.x * blockDim.x + threadIdx.x;
    if (t >= NPTS) return;
    float px = pts[3 * t + 0];
    float py = pts[3 * t + 1];
    float pz = pts[3 * t + 2];
    // exact normalization (same ops as compute kernels -> bit-identical)
    float xs = __fmul_rn(__fadd_rn(px, 1.0f), 0.5f);
    float ys = __fmul_rn(__fadd_rn(py, 1.0f), 0.5f);
    float zs = __fmul_rn(__fadd_rn(pz, 1.0f), 0.5f);

    int cx = min(31, max(0, (int)(xs * 32.0f)));
    int cy = min(31, max(0, (int)(ys * 32.0f)));
    int cz = min(31, max(0, (int)(zs * 32.0f)));
    int b = (cx << 10) | (cy << 5) | cz;

    unsigned c = atomicAdd(&g_cnt[b], 1u);
    if (c < CAP) {
        float4 v;
        v.x = xs; v.y = ys; v.z = zs; v.w = __uint_as_float((unsigned)t);
        g_spts[b * CAP + c] = v;
    } else {
        unsigned o = atomicAdd(&g_ovcnt, 1u);
        g_ov[o] = (unsigned)t;
    }
}

// ---------------- per-level gather/interpolate (exact ops) ----------------

template <bool CG>
__device__ __forceinline__ float2 level_feat(
    float xs, float ys, float zs, float r, const float2* __restrict__ tab)
{
    float posx = __fmul_rn(xs, r);
    float posy = __fmul_rn(ys, r);
    float posz = __fmul_rn(zs, r);

    float fx = floorf(posx), fy = floorf(posy), fz = floorf(posz);
    float wx = __fsub_rn(posx, fx);
    float wy = __fsub_rn(posy, fy);
    float wz = __fsub_rn(posz, fz);

    uint32_t ix = (uint32_t)fx;
    uint32_t iy = (uint32_t)fy;
    uint32_t iz = (uint32_t)fz;

    uint32_t hy0 = iy * PRIME1;
    uint32_t hy1 = hy0 + PRIME1;
    uint32_t hz0 = iz * PRIME2;
    uint32_t hz1 = hz0 + PRIME2;
    uint32_t rest[4];
    rest[0] = hy0 ^ hz0;
    rest[1] = hy0 ^ hz1;
    rest[2] = hy1 ^ hz0;
    rest[3] = hy1 ^ hz1;

    float2 v0[4], v1[4];
    if ((ix & 1u) == 0u) {
        // even ix: x-corners h and h^1 share one aligned float4
        const float4* tab4 = (const float4*)tab;
        #pragma unroll
        for (int i = 0; i < 4; i++) {
            uint32_t b = (ix ^ rest[i]) & HMASK;
            float4 q = CG ? __ldcg(tab4 + (b >> 1)) : __ldg(tab4 + (b >> 1));
            bool lo = (b & 1u) == 0u;
            v0[i] = lo ? make_float2(q.x, q.y) : make_float2(q.z, q.w);
            v1[i] = lo ? make_float2(q.z, q.w) : make_float2(q.x, q.y);
        }
    } else {
        uint32_t ix1 = ix + 1u;
        #pragma unroll
        for (int i = 0; i < 4; i++) {
            v0[i] = CG ? __ldcg(tab + ((ix  ^ rest[i]) & HMASK))
                       : __ldg (tab + ((ix  ^ rest[i]) & HMASK));
            v1[i] = CG ? __ldcg(tab + ((ix1 ^ rest[i]) & HMASK))
                       : __ldg (tab + ((ix1 ^ rest[i]) & HMASK));
        }
    }

    float ux0 = 1.0f - wx, ux1 = wx;
    float uy0 = 1.0f - wy, uy1 = wy;
    float uz0 = 1.0f - wz, uz1 = wz;

    float w000 = ux0 * uy0 * uz0;
    float w001 = ux0 * uy0 * uz1;
    float w010 = ux0 * uy1 * uz0;
    float w011 = ux0 * uy1 * uz1;
    float w100 = ux1 * uy0 * uz0;
    float w101 = ux1 * uy0 * uz1;
    float w110 = ux1 * uy1 * uz0;
    float w111 = ux1 * uy1 * uz1;

    float2 acc;
    acc.x = w000 * v0[0].x + w001 * v0[1].x + w010 * v0[2].x + w011 * v0[3].x
          + w100 * v1[0].x + w101 * v1[1].x + w110 * v1[2].x + w111 * v1[3].x;
    acc.y = w000 * v0[0].y + w001 * v0[1].y + w010 * v0[2].y + w011 * v0[3].y
          + w100 * v1[0].y + w101 * v1[1].y + w110 * v1[2].y + w111 * v1[3].y;
    return acc;
}

__device__ __forceinline__ void coarse_point(
    float xs, float ys, float zs, unsigned p,
    const float2* __restrict__ tables, float2* __restrict__ out,
    const ResArr& res)
{
    float2 f0 = level_feat<false>(xs, ys, zs, res.r[0], tables);
    float2 f1 = level_feat<false>(xs, ys, zs, res.r[1], tables + (size_t)1 * TSIZE);
    float2 f2 = level_feat<false>(xs, ys, zs, res.r[2], tables + (size_t)2 * TSIZE);
    float2 f3 = level_feat<false>(xs, ys, zs, res.r[3], tables + (size_t)3 * TSIZE);
    float4* ob = (float4*)(out + (size_t)p * NLEV);  // first 32B = levels 0-3
    ob[0] = make_float4(f0.x, f0.y, f1.x, f1.y);
    ob[1] = make_float4(f2.x, f2.y, f3.x, f3.y);
}

// ---------------- coarse: levels 0-3, one warp = one bucket ----------------

__global__ __launch_bounds__(256) void ingp_coarse_kernel(
    const float*  __restrict__ pts,
    const float2* __restrict__ tables,
    float2*       __restrict__ out,
    ResArr res)
{
    int t = blockIdx.x * blockDim.x + threadIdx.x;   // NSLOTS threads
    int b = t >> 5;                                  // bucket = warp id
    int j = t & 31;

    unsigned c = g_cnt[b];                           // same addr per warp -> broadcast
    if (j < (int)min(c, (unsigned)CAP)) {
        float4 P = g_spts[t];
        coarse_point(P.x, P.y, P.z, __float_as_uint(P.w), tables, out, res);
    }

    // Fused overflow tail: first n_ov threads each handle one spilled point.
    unsigned n_ov = g_ovcnt;
    if ((unsigned)t < n_ov) {
        unsigned p = g_ov[t];
        float xs = __fmul_rn(__fadd_rn(pts[3 * p + 0], 1.0f), 0.5f);
        float ys = __fmul_rn(__fadd_rn(pts[3 * p + 1], 1.0f), 0.5f);
        float zs = __fmul_rn(__fadd_rn(pts[3 * p + 2], 1.0f), 0.5f);
        coarse_point(xs, ys, zs, p, tables, out, res);
    }
}

// ---------------- fine: levels 4-15, 12 threads per point ----------------

__global__ __launch_bounds__(256) void ingp_fine_kernel(
    const float*  __restrict__ pts,
    const float2* __restrict__ tables,
    float2*       __restrict__ out,
    ResArr res)
{
    int t = blockIdx.x * blockDim.x + threadIdx.x;   // NPTS*12, exact grid
    int n = t / 12;
    int l = 4 + (t - n * 12);

    float px = pts[3 * n + 0];   // 12 lanes share -> broadcast
    float py = pts[3 * n + 1];
    float pz = pts[3 * n + 2];
    float xs = __fmul_rn(__fadd_rn(px, 1.0f), 0.5f);
    float ys = __fmul_rn(__fadd_rn(py, 1.0f), 0.5f);
    float zs = __fmul_rn(__fadd_rn(pz, 1.0f), 0.5f);

    float2 acc = level_feat<true>(xs, ys, zs, res.r[l], tables + (size_t)l * TSIZE);

    out[(size_t)n * NLEV + l] = acc;   // 12 consecutive float2 per point
}

// ---------------- host ----------------

extern "C" void kernel_launch(void* const* d_in, const int* in_sizes, int n_in,
                              void* d_out, int out_size)
{
    const float*  pts    = (const float*)d_in[0];   // [N,3]
    const float2* tables = (const float2*)d_in[1];  // [L,T,2] -> [L,T] float2
    float2*       out    = (float2*)d_out;

    // Replicate numpy RES exactly (float64 libm chain)
    ResArr res;
    {
        double growth = exp((log(2048.0) - log(16.0)) / 15.0);
        for (int l = 0; l < NLEV; l++)
            res.r[l] = (float)floor(16.0 * pow(growth, (double)l));
    }

    zero_kernel<<<(NB + 1 + 1023) / 1024, 1024>>>();
    bin_kernel <<<NPTS / 256, 256>>>(pts);
    ingp_coarse_kernel<<<NSLOTS / 256, 256>>>(pts, tables, out, res);
    ingp_fine_kernel  <<<NPTS * 12 / 256, 256>>>(pts, tables, out, res);
}

// round 12
// speedup vs baseline: 1.1122x; 1.0046x over previous
#include <cuda_runtime.h>
#include <math.h>
#include <stdint.h>

// INGP hashgrid encoding.
//   out[n, l*2+f] = sum_{8 corners} w_c * tables[l, hash(corner)&(T-1), f]
// N=524288, L=16, T=2^19, F=2.
//
// Two parallel graph branches (fork/join with events during stream capture):
//   side stream : zero -> bin -> coarse (levels 0-3, warp = spatial bucket ->
//                 corner gathers merge in the l1tex coalescer; issue-bound,
//                 ~37us total) — hidden under the fine kernel.
//   main stream : fine (levels 4-15, 12 threads/point; l1tex-wavefront-bound
//                 at ~0.97 wf/cyc/SM, ~138us).
// The branches write disjoint byte ranges of each 128B output row
// (bytes 0-31 vs 32-127), so no ordering is needed between them.

#define NPTS   524288
#define NLEV   16
#define TSIZE  (1u << 19)
#define HMASK  (TSIZE - 1u)
#define PRIME1 2654435761u
#define PRIME2 805459861u

#define NB     32768          // 32^3 buckets
#define CAP    32             // slots per bucket (= warp size)
#define NSLOTS (NB * CAP)     // 1048576

struct ResArr { float r[NLEV]; };

__device__ unsigned g_cnt[NB];
__device__ unsigned g_ovcnt;
__device__ unsigned g_ov[NPTS];
__device__ float4   g_spts[NSLOTS];   // xs,ys,zs normalized; w = point idx bits

// ---------------- binning ----------------

__global__ void zero_kernel()
{
    int i = blockIdx.x * blockDim.x + threadIdx.x;
    if (i < NB) g_cnt[i] = 0;
    if (i == NB) g_ovcnt = 0;
}

__global__ void bin_kernel(const float* __restrict__ pts)
{
    int t = blockIdx.x * blockDim.x + threadIdx.x;
    if (t >= NPTS) return;
    float px = pts[3 * t + 0];
    float py = pts[3 * t + 1];
    float pz = pts[3 * t + 2];
    // exact normalization (same ops as compute kernels -> bit-identical)
    float xs = __fmul_rn(__fadd_rn(px, 1.0f), 0.5f);
    float ys = __fmul_rn(__fadd_rn(py, 1.0f), 0.5f);
    float zs = __fmul_rn(__fadd_rn(pz, 1.0f), 0.5f);

    int cx = min(31, max(0, (int)(xs * 32.0f)));
    int cy = min(31, max(0, (int)(ys * 32.0f)));
    int cz = min(31, max(0, (int)(zs * 32.0f)));
    int b = (cx << 10) | (cy << 5) | cz;

    unsigned c = atomicAdd(&g_cnt[b], 1u);
    if (c < CAP) {
        float4 v;
        v.x = xs; v.y = ys; v.z = zs; v.w = __uint_as_float((unsigned)t);
        g_spts[b * CAP + c] = v;
    } else {
        unsigned o = atomicAdd(&g_ovcnt, 1u);
        g_ov[o] = (unsigned)t;
    }
}

// ---------------- per-level gather/interpolate (exact ops) ----------------

template <bool CG>
__device__ __forceinline__ float2 level_feat(
    float xs, float ys, float zs, float r, const float2* __restrict__ tab)
{
    float posx = __fmul_rn(xs, r);
    float posy = __fmul_rn(ys, r);
    float posz = __fmul_rn(zs, r);

    float fx = floorf(posx), fy = floorf(posy), fz = floorf(posz);
    float wx = __fsub_rn(posx, fx);
    float wy = __fsub_rn(posy, fy);
    float wz = __fsub_rn(posz, fz);

    uint32_t ix = (uint32_t)fx;
    uint32_t iy = (uint32_t)fy;
    uint32_t iz = (uint32_t)fz;

    uint32_t hy0 = iy * PRIME1;
    uint32_t hy1 = hy0 + PRIME1;
    uint32_t hz0 = iz * PRIME2;
    uint32_t hz1 = hz0 + PRIME2;
    uint32_t rest[4];
    rest[0] = hy0 ^ hz0;
    rest[1] = hy0 ^ hz1;
    rest[2] = hy1 ^ hz0;
    rest[3] = hy1 ^ hz1;

    float2 v0[4], v1[4];
    if ((ix & 1u) == 0u) {
        // even ix: x-corners h and h^1 share one aligned float4
        const float4* tab4 = (const float4*)tab;
        #pragma unroll
        for (int i = 0; i < 4; i++) {
            uint32_t b = (ix ^ rest[i]) & HMASK;
            float4 q = CG ? __ldcg(tab4 + (b >> 1)) : __ldg(tab4 + (b >> 1));
            bool lo = (b & 1u) == 0u;
            v0[i] = lo ? make_float2(q.x, q.y) : make_float2(q.z, q.w);
            v1[i] = lo ? make_float2(q.z, q.w) : make_float2(q.x, q.y);
        }
    } else {
        uint32_t ix1 = ix + 1u;
        #pragma unroll
        for (int i = 0; i < 4; i++) {
            v0[i] = CG ? __ldcg(tab + ((ix  ^ rest[i]) & HMASK))
                       : __ldg (tab + ((ix  ^ rest[i]) & HMASK));
            v1[i] = CG ? __ldcg(tab + ((ix1 ^ rest[i]) & HMASK))
                       : __ldg (tab + ((ix1 ^ rest[i]) & HMASK));
        }
    }

    float ux0 = 1.0f - wx, ux1 = wx;
    float uy0 = 1.0f - wy, uy1 = wy;
    float uz0 = 1.0f - wz, uz1 = wz;

    float w000 = ux0 * uy0 * uz0;
    float w001 = ux0 * uy0 * uz1;
    float w010 = ux0 * uy1 * uz0;
    float w011 = ux0 * uy1 * uz1;
    float w100 = ux1 * uy0 * uz0;
    float w101 = ux1 * uy0 * uz1;
    float w110 = ux1 * uy1 * uz0;
    float w111 = ux1 * uy1 * uz1;

    float2 acc;
    acc.x = w000 * v0[0].x + w001 * v0[1].x + w010 * v0[2].x + w011 * v0[3].x
          + w100 * v1[0].x + w101 * v1[1].x + w110 * v1[2].x + w111 * v1[3].x;
    acc.y = w000 * v0[0].y + w001 * v0[1].y + w010 * v0[2].y + w011 * v0[3].y
          + w100 * v1[0].y + w101 * v1[1].y + w110 * v1[2].y + w111 * v1[3].y;
    return acc;
}

__device__ __forceinline__ void coarse_point(
    float xs, float ys, float zs, unsigned p,
    const float2* __restrict__ tables, float2* __restrict__ out,
    const ResArr& res)
{
    float2 f0 = level_feat<false>(xs, ys, zs, res.r[0], tables);
    float2 f1 = level_feat<false>(xs, ys, zs, res.r[1], tables + (size_t)1 * TSIZE);
    float2 f2 = level_feat<false>(xs, ys, zs, res.r[2], tables + (size_t)2 * TSIZE);
    float2 f3 = level_feat<false>(xs, ys, zs, res.r[3], tables + (size_t)3 * TSIZE);
    float4* ob = (float4*)(out + (size_t)p * NLEV);  // first 32B = levels 0-3
    ob[0] = make_float4(f0.x, f0.y, f1.x, f1.y);
    ob[1] = make_float4(f2.x, f2.y, f3.x, f3.y);
}

// ---------------- coarse: levels 0-3, one warp = one bucket ----------------

__global__ __launch_bounds__(256) void ingp_coarse_kernel(
    const float*  __restrict__ pts,
    const float2* __restrict__ tables,
    float2*       __restrict__ out,
    ResArr res)
{
    int t = blockIdx.x * blockDim.x + threadIdx.x;   // NSLOTS threads
    int b = t >> 5;                                  // bucket = warp id
    int j = t & 31;

    unsigned c = g_cnt[b];                           // same addr per warp -> broadcast
    if (j < (int)min(c, (unsigned)CAP)) {
        float4 P = g_spts[t];
        coarse_point(P.x, P.y, P.z, __float_as_uint(P.w), tables, out, res);
    }

    // Fused overflow tail: first n_ov threads each handle one spilled point.
    unsigned n_ov = g_ovcnt;
    if ((unsigned)t < n_ov) {
        unsigned p = g_ov[t];
        float xs = __fmul_rn(__fadd_rn(pts[3 * p + 0], 1.0f), 0.5f);
        float ys = __fmul_rn(__fadd_rn(pts[3 * p + 1], 1.0f), 0.5f);
        float zs = __fmul_rn(__fadd_rn(pts[3 * p + 2], 1.0f), 0.5f);
        coarse_point(xs, ys, zs, p, tables, out, res);
    }
}

// ---------------- fine: levels 4-15, 12 threads per point ----------------

__global__ __launch_bounds__(256) void ingp_fine_kernel(
    const float*  __restrict__ pts,
    const float2* __restrict__ tables,
    float2*       __restrict__ out,
    ResArr res)
{
    int t = blockIdx.x * blockDim.x + threadIdx.x;   // NPTS*12, exact grid
    int n = t / 12;
    int l = 4 + (t - n * 12);

    float px = pts[3 * n + 0];   // 12 lanes share -> broadcast
    float py = pts[3 * n + 1];
    float pz = pts[3 * n + 2];
    float xs = __fmul_rn(__fadd_rn(px, 1.0f), 0.5f);
    float ys = __fmul_rn(__fadd_rn(py, 1.0f), 0.5f);
    float zs = __fmul_rn(__fadd_rn(pz, 1.0f), 0.5f);

    float2 acc = level_feat<true>(xs, ys, zs, res.r[l], tables + (size_t)l * TSIZE);

    out[(size_t)n * NLEV + l] = acc;   // 12 consecutive float2 per point
}

// ---------------- host ----------------

extern "C" void kernel_launch(void* const* d_in, const int* in_sizes, int n_in,
                              void* d_out, int out_size)
{
    const float*  pts    = (const float*)d_in[0];   // [N,3]
    const float2* tables = (const float2*)d_in[1];  // [L,T,2] -> [L,T] float2
    float2*       out    = (float2*)d_out;

    // Replicate numpy RES exactly (float64 libm chain)
    ResArr res;
    {
        double growth = exp((log(2048.0) - log(16.0)) / 15.0);
        for (int l = 0; l < NLEV; l++)
            res.r[l] = (float)floor(16.0 * pow(growth, (double)l));
    }

    // Host-side handles, created once. Only host/driver resources (no device
    // memory). The captured GPU work is identical on every call.
    static cudaStream_t s_side = nullptr;
    static cudaEvent_t  s_fork = nullptr, s_join = nullptr;
    if (!s_side) {
        cudaStreamCreateWithFlags(&s_side, cudaStreamNonBlocking);
        cudaEventCreateWithFlags(&s_fork, cudaEventDisableTiming);
        cudaEventCreateWithFlags(&s_join, cudaEventDisableTiming);
    }

    // Fork: side stream inherits capture from the launch (default) stream.
    cudaEventRecord(s_fork, 0);
    cudaStreamWaitEvent(s_side, s_fork, 0);

    // Branch A (side): binning + coarse levels 0-3 (issue-bound, ~37us)
    zero_kernel<<<(NB + 1 + 1023) / 1024, 1024, 0, s_side>>>();
    bin_kernel <<<NPTS / 256, 256, 0, s_side>>>(pts);
    ingp_coarse_kernel<<<NSLOTS / 256, 256, 0, s_side>>>(pts, tables, out, res);
    cudaEventRecord(s_join, s_side);

    // Branch B (main): fine levels 4-15 (l1tex-bound, ~138us) runs concurrently
    ingp_fine_kernel<<<NPTS * 12 / 256, 256>>>(pts, tables, out, res);

    // Join: downstream ops on the main stream see both branches complete.
    cudaStreamWaitEvent(0, s_join, 0);
}

// round 14
// speedup vs baseline: 1.1500x; 1.0340x over previous
#include <cuda_runtime.h>
#include <math.h>
#include <stdint.h>

// INGP hashgrid encoding — single main kernel (R2 champion shape) plus a tiny
// densify prefix.
//   out[n, l*2+f] = sum_{8 corners} w_c * tables[l, hash(corner)&(T-1), f]
// N=524288, L=16, T=2^19, F=2.
//
// Levels 0-1 are densified into a compact 143KB array (z-stride padded even):
//   - fully L1-resident -> every gather is an L1-hit wavefront (~2x cheaper
//     than a miss wavefront, per R2/R9 measurements)
//   - even strides => when iz is even, all four z-pairs are aligned float4s
//     (4 loads instead of 8)
// Levels 2-15 stay hashed with the even-ix float4 pairing (hash uses prime 1
// on x: even ix -> x-corners at h and h^1 share one aligned float4) and use
// .cg so they cannot evict the dense tables from L1.

#define NPTS   524288
#define NLEV   16
#define TSIZE  (1u << 19)
#define HMASK  (TSIZE - 1u)
#define PRIME1 2654435761u
#define PRIME2 805459861u

// dense level geometry (res0=16 -> 17 corners, res1=22 -> 23 corners),
// z padded to even stride so parity(idx) == parity(iz) for all corners
#define D0     17
#define D0Z    18                 // padded z-extent (even)
#define SX0    (D0 * D0Z)         // 306 (even)
#define SY0    D0Z                // 18  (even)
#define N0     (D0 * SX0)         // 5202 float2
#define D1     23
#define D1Z    24
#define SX1    (D1 * D1Z)         // 552 (even)
#define SY1    D1Z                // 24  (even)
#define N1     (D1 * SX1)         // 12696 float2
#define NDENSE (N0 + N1)          // 17898 float2 = 143184 B

struct ResArr { float r[NLEV]; };

__device__ float2 g_dense[NDENSE];

// ---- prefix: densify levels 0,1  (g_dense[cell] = tables[l][hash(cell)]) ----
__global__ void ingp_densify_kernel(const float2* __restrict__ tables)
{
    int id = blockIdx.x * blockDim.x + threadIdx.x;
    // l0: 17^3 = 4913 cells, l1: 23^3 = 12167 cells -> 17080 useful threads
    if (id < D0 * D0 * D0) {
        int z = id % D0, y = (id / D0) % D0, x = id / (D0 * D0);
        uint32_t h = ((uint32_t)x ^ ((uint32_t)y * PRIME1) ^ ((uint32_t)z * PRIME2)) & HMASK;
        g_dense[x * SX0 + y * SY0 + z] = tables[h];
    } else if (id < D0 * D0 * D0 + D1 * D1 * D1) {
        int j = id - D0 * D0 * D0;
        int z = j % D1, y = (j / D1) % D1, x = j / (D1 * D1);
        uint32_t h = ((uint32_t)x ^ ((uint32_t)y * PRIME1) ^ ((uint32_t)z * PRIME2)) & HMASK;
        g_dense[N0 + x * SX1 + y * SY1 + z] = tables[(size_t)TSIZE + h];
    }
}

// ---- main kernel: 16 threads per point, lane = level ----
__global__ __launch_bounds__(256) void ingp_encode_kernel(
    const float*  __restrict__ pts,     // [N,3]
    const float2* __restrict__ tables,  // [L,T] float2
    float2*       __restrict__ out,     // [N,16] float2
    ResArr res)
{
    int t = blockIdx.x * blockDim.x + threadIdx.x;   // exact grid: N*16/256
    int n = t >> 4;          // point
    int l = t & 15;          // level

    // 16 consecutive threads share a point -> L1 broadcast
    float px = pts[3 * n + 0];
    float py = pts[3 * n + 1];
    float pz = pts[3 * n + 2];

    // x = (p + 1)/2 — exact ops, no FMA contraction
    float xs = __fmul_rn(__fadd_rn(px, 1.0f), 0.5f);
    float ys = __fmul_rn(__fadd_rn(py, 1.0f), 0.5f);
    float zs = __fmul_rn(__fadd_rn(pz, 1.0f), 0.5f);

    float r = res.r[l];
    float posx = __fmul_rn(xs, r);
    float posy = __fmul_rn(ys, r);
    float posz = __fmul_rn(zs, r);

    float fx = floorf(posx), fy = floorf(posy), fz = floorf(posz);
    float wx = __fsub_rn(posx, fx);
    float wy = __fsub_rn(posy, fy);
    float wz = __fsub_rn(posz, fz);

    uint32_t ix = (uint32_t)fx;
    uint32_t iy = (uint32_t)fy;
    uint32_t iz = (uint32_t)fz;

    // Corner values in CORNERS order: v0 = x-corner 0, v1 = x-corner 1,
    // each indexed by (y,z) pair: [y0z0, y0z1, y1z0, y1z1]
    float2 v0[4], v1[4];

    if (l < 2) {
        // ---- dense L1-resident path ----
        int sx   = (l == 0) ? SX0 : SX1;
        int sy   = (l == 0) ? SY0 : SY1;
        int base = (l == 0) ? 0 : N0;
        int c00  = base + (int)ix * sx + (int)iy * sy + (int)iz;  // (x0,y0,z0)
        if ((iz & 1u) == 0u) {
            // even iz + even strides -> all 4 z-pairs are aligned float4
            const float4* d4 = (const float4*)g_dense;
            float4 qa = d4[(c00            ) >> 1];   // (x0,y0,z0),(x0,y0,z1)
            float4 qb = d4[(c00 + sy       ) >> 1];   // (x0,y1,*)
            float4 qc = d4[(c00 + sx       ) >> 1];   // (x1,y0,*)
            float4 qd = d4[(c00 + sx + sy  ) >> 1];   // (x1,y1,*)
            v0[0] = make_float2(qa.x, qa.y); v0[1] = make_float2(qa.z, qa.w);
            v0[2] = make_float2(qb.x, qb.y); v0[3] = make_float2(qb.z, qb.w);
            v1[0] = make_float2(qc.x, qc.y); v1[1] = make_float2(qc.z, qc.w);
            v1[2] = make_float2(qd.x, qd.y); v1[3] = make_float2(qd.z, qd.w);
        } else {
            v0[0] = g_dense[c00];
            v0[1] = g_dense[c00 + 1];
            v0[2] = g_dense[c00 + sy];
            v0[3] = g_dense[c00 + sy + 1];
            v1[0] = g_dense[c00 + sx];
            v1[1] = g_dense[c00 + sx + 1];
            v1[2] = g_dense[c00 + sx + sy];
            v1[3] = g_dense[c00 + sx + sy + 1];
        }
    } else {
        // ---- hashed path (levels 2-15), .cg to keep L1 for g_dense ----
        uint32_t hy0 = iy * PRIME1;
        uint32_t hy1 = hy0 + PRIME1;
        uint32_t hz0 = iz * PRIME2;
        uint32_t hz1 = hz0 + PRIME2;
        uint32_t rest[4];
        rest[0] = hy0 ^ hz0;
        rest[1] = hy0 ^ hz1;
        rest[2] = hy1 ^ hz0;
        rest[3] = hy1 ^ hz1;

        const float2* __restrict__ tab = tables + (size_t)l * TSIZE;

        if ((ix & 1u) == 0u) {
            // even ix: x-corners h and h^1 share one aligned float4
            const float4* tab4 = (const float4*)tab;
            #pragma unroll
            for (int i = 0; i < 4; i++) {
                uint32_t b = (ix ^ rest[i]) & HMASK;
                float4 q = __ldcg(tab4 + (b >> 1));
                bool lo = (b & 1u) == 0u;
                v0[i] = lo ? make_float2(q.x, q.y) : make_float2(q.z, q.w);
                v1[i] = lo ? make_float2(q.z, q.w) : make_float2(q.x, q.y);
            }
        } else {
            uint32_t ix1 = ix + 1u;
            #pragma unroll
            for (int i = 0; i < 4; i++) {
                v0[i] = __ldcg(tab + ((ix  ^ rest[i]) & HMASK));
                v1[i] = __ldcg(tab + ((ix1 ^ rest[i]) & HMASK));
            }
        }
    }

    // Trilinear weights (corner bit set -> w, else 1-w), CORNERS order
    float ux0 = 1.0f - wx, ux1 = wx;
    float uy0 = 1.0f - wy, uy1 = wy;
    float uz0 = 1.0f - wz, uz1 = wz;

    float w000 = ux0 * uy0 * uz0;
    float w001 = ux0 * uy0 * uz1;
    float w010 = ux0 * uy1 * uz0;
    float w011 = ux0 * uy1 * uz1;
    float w100 = ux1 * uy0 * uz0;
    float w101 = ux1 * uy0 * uz1;
    float w110 = ux1 * uy1 * uz0;
    float w111 = ux1 * uy1 * uz1;

    float2 acc;
    acc.x = w000 * v0[0].x + w001 * v0[1].x + w010 * v0[2].x + w011 * v0[3].x
          + w100 * v1[0].x + w101 * v1[1].x + w110 * v1[2].x + w111 * v1[3].x;
    acc.y = w000 * v0[0].y + w001 * v0[1].y + w010 * v0[2].y + w011 * v0[3].y
          + w100 * v1[0].y + w101 * v1[1].y + w110 * v1[2].y + w111 * v1[3].y;

    out[(size_t)n * NLEV + l] = acc;   // 16 consecutive float2 per point group
}

// ---------------- host ----------------

extern "C" void kernel_launch(void* const* d_in, const int* in_sizes, int n_in,
                              void* d_out, int out_size)
{
    const float*  pts    = (const float*)d_in[0];   // [N,3]
    const float2* tables = (const float2*)d_in[1];  // [L,T,2] -> [L,T] float2

    // Replicate numpy RES exactly (float64 libm chain)
    ResArr res;
    {
        double growth = exp((log(2048.0) - log(16.0)) / 15.0);
        for (int l = 0; l < NLEV; l++)
            res.r[l] = (float)floor(16.0 * pow(growth, (double)l));
    }

    int ncells = D0 * D0 * D0 + D1 * D1 * D1;       // 17080
    ingp_densify_kernel<<<(ncells + 255) / 256, 256>>>(tables);

    int total = NPTS * NLEV;                        // 8388608
    ingp_encode_kernel<<<total / 256, 256>>>(pts, tables, (float2*)d_out, res);
}